// round 10
// baseline (speedup 1.0000x reference)
#include <cuda_runtime.h>

#define H 1024
#define V 50257
#define LCTX 4096

#define NBLK 740            // 148 SMs x 5 co-resident 256-thr blocks -> sw barrier safe
#define TPB  256
#define NWARP (NBLK * 8)    // 5920 warps
#define CHUNK 8
#define NCHUNK ((V + CHUNK - 1) / CHUNK)   // 6283 logits chunks
#define SLICE 9                            // chunks per block in stage-6a (740*9 >= 6283)

// ---------------- device scratch (allocation-free, 16B aligned) ----------------
__device__ __align__(16) float g_e[LCTX];
__device__ __align__(16) float g_cat[2 * H];
__device__ __align__(16) float g_x[H];
__device__ __align__(16) float g_gh[3 * H];
__device__ __align__(16) float g_h[H];
__device__ float g_bm[NBLK];
__device__ float g_bs[NBLK];
__device__ float g_cm[NCHUNK];
__device__ float g_cs[NCHUNK];
__device__ unsigned g_work = 0;
__device__ unsigned g_bar_count = 0;
__device__ unsigned g_bar_gen   = 0;

__device__ __forceinline__ void grid_barrier() {
    __threadfence();
    __syncthreads();
    if (threadIdx.x == 0) {
        unsigned gen = *(volatile unsigned*)&g_bar_gen;
        if (atomicAdd(&g_bar_count, 1u) == NBLK - 1) {
            g_bar_count = 0;
            __threadfence();
            atomicExch(&g_bar_gen, gen + 1);
        } else {
            while (*(volatile unsigned*)&g_bar_gen == gen) { __nanosleep(64); }
        }
        __threadfence();
    }
    __syncthreads();
}

__device__ __forceinline__ float warp_sum(float s) {
#pragma unroll
    for (int o = 16; o; o >>= 1) s += __shfl_xor_sync(0xffffffffu, s, o);
    return s;
}
__device__ __forceinline__ void pair_combine(float& m, float& s, float om, float os) {
    float nm = fmaxf(m, om);
    s = s * expf(m - nm) + os * expf(om - nm);   // -1e30 sentinel keeps this NaN-free
    m = nm;
}
// xor-shuffle combine of (m,s) pairs across lanes (fixed order -> deterministic)
__device__ __forceinline__ void warp_pair_reduce(float& m, float& s, int width) {
#pragma unroll
    for (int o = 16; o; o >>= 1) {
        if (o < width || width == 32) {
            float om = __shfl_xor_sync(0xffffffffu, m, o);
            float os = __shfl_xor_sync(0xffffffffu, s, o);
            pair_combine(m, s, om, os);
        }
    }
}

template <int C4>
__device__ __forceinline__ float row_dot(const float4* __restrict__ row,
                                         const float4* __restrict__ vec, int lane) {
    float s = 0.0f;
#pragma unroll
    for (int i = 0; i < C4 / 32; ++i) {
        float4 w = __ldg(&row[lane + i * 32]);
        float4 x = vec[lane + i * 32];
        s = fmaf(w.x, x.x, s); s = fmaf(w.y, x.y, s);
        s = fmaf(w.z, x.z, s); s = fmaf(w.w, x.w, s);
    }
    return warp_sum(s);
}

// ================= everything in ONE kernel, 5 blocks/SM =================
__global__ void __launch_bounds__(TPB, 5)
fused_kernel(const int* __restrict__ y, const float* __restrict__ s_bef,
             const float* __restrict__ h_all, const float* __restrict__ emb_W,
             const float* __restrict__ alignW, const float* __restrict__ new_W,
             const float* __restrict__ new_b, const float* __restrict__ W_ih,
             const float* __restrict__ b_ih, const float* __restrict__ W_hh,
             const float* __restrict__ b_hh, const float* __restrict__ out_W,
             const float* __restrict__ out_b, float* __restrict__ out) {
    __shared__ float sbuf[2 * H];
    __shared__ float sred[40];
    __shared__ float smp[8], ssp[8];

    const int t    = threadIdx.x;
    const int bid  = blockIdx.x;
    const int wid  = t >> 5;
    const int lane = t & 31;
    const int gw   = bid * 8 + wid;     // 0..5919
    float4* sb4 = reinterpret_cast<float4*>(sbuf);

    // ---------- phase 1: e = h_all@Wh (+online stats) ; gh = W_hh@s_prev + b_hh ; setup ----------
    sb4[t]       = reinterpret_cast<const float4*>(alignW)[t];        // Wh
    sb4[256 + t] = reinterpret_cast<const float4*>(s_bef)[t];         // s_prev
    __syncthreads();

    if (bid == 1)
        reinterpret_cast<float4*>(g_cat)[t] =
            reinterpret_cast<const float4*>(emb_W)[(size_t)y[0] * 256 + t];
    if (bid == 2)
        reinterpret_cast<float4*>(g_cat)[256 + t] = make_float4(0.f, 0.f, 0.f, 0.f);
    if (bid == 3 && t == 0) g_work = 0;          // reset work-steal counter each launch

    float em = -1e30f, es = 0.0f;                // this warp's online e-stats
    for (int r = gw; r < LCTX + 3 * H; r += NWARP) {
        float s;
        if (r < LCTX)
            s = row_dot<256>(reinterpret_cast<const float4*>(h_all) + (size_t)r * 256, sb4, lane);
        else
            s = row_dot<256>(reinterpret_cast<const float4*>(W_hh) + (size_t)(r - LCTX) * 256, sb4 + 256, lane);
        if (r < LCTX) {
            if (lane == 0) g_e[r] = s;
            pair_combine(em, es, s, 1.0f);       // warp-uniform s; fixed row order
        } else if (lane == 0) {
            g_gh[r - LCTX] = s + b_hh[r - LCTX];
        }
    }
    if (lane == 0) { smp[wid] = em; ssp[wid] = es; }
    __syncthreads();
    if (wid == 0) {
        float pm = (lane < 8) ? smp[lane] : -1e30f;
        float ps = (lane < 8) ? ssp[lane] : 0.0f;
        warp_pair_reduce(pm, ps, 8);
        if (lane == 0) { g_bm[bid] = pm; g_bs[bid] = ps; }
    }
    grid_barrier();

    // ---------- phase 2: combine 740 e-stat pairs (6KB, fixed order) ; ctx ; a-out ----------
    {
        float pm = -1e30f, ps = 0.0f;
        for (int i = t; i < NBLK; i += TPB) pair_combine(pm, ps, g_bm[i], g_bs[i]);
        warp_pair_reduce(pm, ps, 32);
        if (lane == 0) { smp[wid] = pm; ssp[wid] = ps; }
        __syncthreads();
        if (wid == 0) {
            float qm = (lane < 8) ? smp[lane] : -1e30f;
            float qs = (lane < 8) ? ssp[lane] : 0.0f;
            warp_pair_reduce(qm, qs, 8);
            if (lane == 0) { sred[32] = qm; sred[33] = qs; }
        }
        __syncthreads();
    }
    const float M    = sred[32];
    const float invS = 1.0f / sred[33];
    __syncthreads();

    {   // ctx spread over 716 blocks: chunk c = bid>>2 (23 l-rows), col group jg = bid&3
        const int c  = bid >> 2;
        const int jg = bid & 3;
        const int l0 = c * 23;
        if (l0 < LCTX) {
            const int nrows = min(23, LCTX - l0);
            if (t < nrows) sbuf[t] = expf(g_e[l0 + t] - M) * invS;
            __syncthreads();
            const int j = jg * 256 + t;
            const float* hp = h_all + (size_t)l0 * H + j;
            float acc = 0.0f;
            for (int l = 0; l < nrows; ++l) acc = fmaf(sbuf[l], hp[(size_t)l * H], acc);
            atomicAdd(&g_cat[H + j], acc);
        } else if (bid >= 716 && bid < 732) {
            int l = (bid - 716) * 256 + t;
            out[V + H + l] = expf(g_e[l] - M) * invS;   // attention weights output
        }
    }
    grid_barrier();

    // ---------- phase 3: x = new_W @ [emb; c] + new_b ----------
    sb4[t]       = reinterpret_cast<const float4*>(g_cat)[t];
    sb4[256 + t] = reinterpret_cast<const float4*>(g_cat)[256 + t];
    __syncthreads();
    if (gw < H) {
        float acc = row_dot<512>(reinterpret_cast<const float4*>(new_W) + (size_t)gw * 512, sb4, lane);
        if (lane == 0) g_x[gw] = acc + new_b[gw];
    }
    grid_barrier();

    // ---------- phase 4: gi rows (3 per owning warp) + GRU gates -> h_new ----------
    sb4[t] = reinterpret_cast<const float4*>(g_x)[t];
    __syncthreads();
    if (gw < H) {
        const float4* Wv = reinterpret_cast<const float4*>(W_ih);
        float d0 = row_dot<256>(Wv + (size_t)gw * 256, sb4, lane);
        float d1 = row_dot<256>(Wv + (size_t)(gw + H) * 256, sb4, lane);
        float d2 = row_dot<256>(Wv + (size_t)(gw + 2 * H) * 256, sb4, lane);
        if (lane == 0) {
            float rr = 1.0f / (1.0f + expf(-(d0 + b_ih[gw] + g_gh[gw])));
            float zz = 1.0f / (1.0f + expf(-(d1 + b_ih[gw + H] + g_gh[gw + H])));
            float nn = tanhf(d2 + b_ih[gw + 2 * H] + rr * g_gh[gw + 2 * H]);
            float hv = (1.0f - zz) * nn + zz * s_bef[gw];
            g_h[gw]    = hv;
            out[V + gw] = hv;
        }
    }
    grid_barrier();

    // ---------- phase 5: logits GEMV, WORK-STEALING 8-row chunks ----------
    sb4[t] = reinterpret_cast<const float4*>(g_h)[t];
    __syncthreads();

    for (;;) {
        unsigned c;
        if (lane == 0) c = atomicAdd(&g_work, 1u);
        c = __shfl_sync(0xffffffffu, c, 0);
        if (c >= NCHUNK) break;
        const int r0 = (int)c * CHUNK;

        float acc[CHUNK];
#pragma unroll
        for (int k = 0; k < CHUNK; ++k) acc[k] = 0.0f;
#pragma unroll
        for (int k = 0; k < CHUNK; ++k) {
            const int r = r0 + k;
            if (r < V) {
                const float4* Wr = reinterpret_cast<const float4*>(out_W) + (size_t)r * 256;
#pragma unroll
                for (int i = 0; i < 8; ++i) {
                    float4 w = __ldcs(&Wr[lane + i * 32]);
                    float4 x = sb4[lane + i * 32];
                    acc[k] = fmaf(w.x, x.x, acc[k]); acc[k] = fmaf(w.y, x.y, acc[k]);
                    acc[k] = fmaf(w.z, x.z, acc[k]); acc[k] = fmaf(w.w, x.w, acc[k]);
                }
            }
        }
#pragma unroll
        for (int k = 0; k < CHUNK; ++k) acc[k] = warp_sum(acc[k]);
        if (lane == 0) {
            float cm = -1e30f, cs = 0.0f;
#pragma unroll
            for (int k = 0; k < CHUNK; ++k) {
                const int r = r0 + k;
                if (r < V) {
                    float v = acc[k] + out_b[r];
                    out[r] = v;                      // raw logit
                    pair_combine(cm, cs, v, 1.0f);   // fixed in-chunk order
                }
            }
            g_cm[c] = cm; g_cs[c] = cs;              // keyed by chunk id -> deterministic
        }
    }
    grid_barrier();

    // ---------- phase 6a: block bid combines its slice of chunk pairs ----------
    if (wid == 0) {
        const int c0 = bid * SLICE;
        float pm = -1e30f, ps = 0.0f;
        if (lane < SLICE) {
            const int c = c0 + lane;
            if (c < NCHUNK) { pm = g_cm[c]; ps = g_cs[c]; }
        }
        warp_pair_reduce(pm, ps, 16);
        if (lane == 0) { g_bm[bid] = pm; g_bs[bid] = ps; }
    }
    grid_barrier();

    // ---------- phase 6b: combine 740 pairs redundantly (fixed order); subtract ln ----------
    {
        float pm = -1e30f, ps = 0.0f;
        for (int i = t; i < NBLK; i += TPB) pair_combine(pm, ps, g_bm[i], g_bs[i]);
        warp_pair_reduce(pm, ps, 32);
        if (lane == 0) { smp[wid] = pm; ssp[wid] = ps; }
        __syncthreads();
        if (wid == 0) {
            float qm = (lane < 8) ? smp[lane] : -1e30f;
            float qs = (lane < 8) ? ssp[lane] : 0.0f;
            warp_pair_reduce(qm, qs, 8);
            if (lane == 0) sred[34] = qm + logf(qs);
        }
        __syncthreads();
        const float ln = sred[34];
        const int i = bid * TPB + t;                 // 189440 threads >= V: 1 elem each, L2-hot
        if (i < V) out[i] -= ln;
    }
}

// ================= launch: single kernel =================
extern "C" void kernel_launch(void* const* d_in, const int* in_sizes, int n_in,
                              void* d_out, int out_size) {
    const int*   y      = (const int*)d_in[0];
    const float* s_bef  = (const float*)d_in[1];
    const float* h_all  = (const float*)d_in[2];
    const float* emb_W  = (const float*)d_in[3];
    const float* alignW = (const float*)d_in[4];
    // d_in[5] align_b: uniform additive shift -> softmax-invariant, dropped
    const float* new_W  = (const float*)d_in[6];
    const float* new_b  = (const float*)d_in[7];
    const float* W_ih   = (const float*)d_in[8];
    const float* b_ih   = (const float*)d_in[9];
    const float* W_hh   = (const float*)d_in[10];
    const float* b_hh   = (const float*)d_in[11];
    const float* out_W  = (const float*)d_in[12];
    const float* out_b  = (const float*)d_in[13];
    float* out = (float*)d_out;  // [logp(V) | h_new(H) | a(L)]

    fused_kernel<<<NBLK, TPB>>>(y, s_bef, h_all, emb_W, alignW, new_W, new_b,
                                W_ih, b_ih, W_hh, b_hh, out_W, out_b, out);
}

// round 11
// speedup vs baseline: 1.1610x; 1.1610x over previous
#include <cuda_runtime.h>

#define H 1024
#define V 50257
#define LCTX 4096

#define NBLK 740            // 148 SMs x 5 co-resident 256-thr blocks -> sw barrier safe
#define TPB  256
#define NWARP (NBLK * 8)    // 5920 warps
#define NROW_LOG 9          // ceil(V / NWARP), consecutive rows per warp

// ---------------- device scratch (allocation-free, 16B aligned) ----------------
__device__ __align__(16) float g_e[LCTX];
__device__ __align__(16) float g_cat[2 * H];
__device__ __align__(16) float g_x[H];
__device__ __align__(16) float g_gh[3 * H];
__device__ __align__(16) float g_h[H];
__device__ float g_bm[NBLK];
__device__ float g_bs[NBLK];
__device__ unsigned g_bar_count = 0;
__device__ unsigned g_bar_gen   = 0;

__device__ __forceinline__ void grid_barrier() {
    __threadfence();
    __syncthreads();
    if (threadIdx.x == 0) {
        unsigned gen = *(volatile unsigned*)&g_bar_gen;
        if (atomicAdd(&g_bar_count, 1u) == NBLK - 1) {
            g_bar_count = 0;
            __threadfence();
            atomicExch(&g_bar_gen, gen + 1);
        } else {
            while (*(volatile unsigned*)&g_bar_gen == gen) { __nanosleep(64); }
        }
        __threadfence();
    }
    __syncthreads();
}

__device__ __forceinline__ float warp_sum(float s) {
#pragma unroll
    for (int o = 16; o; o >>= 1) s += __shfl_xor_sync(0xffffffffu, s, o);
    return s;
}
__device__ __forceinline__ void pair_combine(float& m, float& s, float om, float os) {
    float nm = fmaxf(m, om);
    s = s * expf(m - nm) + os * expf(om - nm);
    m = nm;
}
__device__ __forceinline__ void warp_pair_reduce8(float& m, float& s) {
#pragma unroll
    for (int o = 4; o; o >>= 1) {
        float om = __shfl_xor_sync(0xffffffffu, m, o);
        float os = __shfl_xor_sync(0xffffffffu, s, o);
        pair_combine(m, s, om, os);
    }
}
__device__ __forceinline__ void warp_pair_reduce32(float& m, float& s) {
#pragma unroll
    for (int o = 16; o; o >>= 1) {
        float om = __shfl_xor_sync(0xffffffffu, m, o);
        float os = __shfl_xor_sync(0xffffffffu, s, o);
        pair_combine(m, s, om, os);
    }
}

template <int C4>
__device__ __forceinline__ float row_dot(const float4* __restrict__ row,
                                         const float4* __restrict__ vec, int lane) {
    float s = 0.0f;
#pragma unroll
    for (int i = 0; i < C4 / 32; ++i) {
        float4 w = __ldg(&row[lane + i * 32]);
        float4 x = vec[lane + i * 32];
        s = fmaf(w.x, x.x, s); s = fmaf(w.y, x.y, s);
        s = fmaf(w.z, x.z, s); s = fmaf(w.w, x.w, s);
    }
    return warp_sum(s);
}

// ================= everything in ONE kernel, 5 blocks/SM =================
__global__ void __launch_bounds__(TPB, 5)
fused_kernel(const int* __restrict__ y, const float* __restrict__ s_bef,
             const float* __restrict__ h_all, const float* __restrict__ emb_W,
             const float* __restrict__ alignW, const float* __restrict__ new_W,
             const float* __restrict__ new_b, const float* __restrict__ W_ih,
             const float* __restrict__ b_ih, const float* __restrict__ W_hh,
             const float* __restrict__ b_hh, const float* __restrict__ out_W,
             const float* __restrict__ out_b, float* __restrict__ out) {
    __shared__ float sbuf[2 * H];
    __shared__ float sred[40];
    __shared__ float smp[8], ssp[8];

    const int t    = threadIdx.x;
    const int bid  = blockIdx.x;
    const int wid  = t >> 5;
    const int lane = t & 31;
    const int gw   = bid * 8 + wid;     // 0..5919
    float4* sb4 = reinterpret_cast<float4*>(sbuf);

    // ---------- phase 1: e = h_all@Wh (online stats) ; gh = W_hh@s_prev + b_hh ; setup ----------
    sb4[t]       = reinterpret_cast<const float4*>(alignW)[t];        // Wh
    sb4[256 + t] = reinterpret_cast<const float4*>(s_bef)[t];         // s_prev
    __syncthreads();

    if (bid == 1)
        reinterpret_cast<float4*>(g_cat)[t] =
            reinterpret_cast<const float4*>(emb_W)[(size_t)y[0] * 256 + t];
    if (bid == 2)
        reinterpret_cast<float4*>(g_cat)[256 + t] = make_float4(0.f, 0.f, 0.f, 0.f);

    float em = -1e30f, es = 0.0f;                // this warp's online e-stats (fixed order)
    for (int r = gw; r < LCTX + 3 * H; r += NWARP) {
        float s;
        if (r < LCTX)
            s = row_dot<256>(reinterpret_cast<const float4*>(h_all) + (size_t)r * 256, sb4, lane);
        else
            s = row_dot<256>(reinterpret_cast<const float4*>(W_hh) + (size_t)(r - LCTX) * 256, sb4 + 256, lane);
        if (r < LCTX) {
            if (lane == 0) g_e[r] = s;
            pair_combine(em, es, s, 1.0f);       // s is warp-uniform after warp_sum
        } else if (lane == 0) {
            g_gh[r - LCTX] = s + b_hh[r - LCTX];
        }
    }
    if (lane == 0) { smp[wid] = em; ssp[wid] = es; }
    __syncthreads();
    if (wid == 0) {
        float pm = (lane < 8) ? smp[lane] : -1e30f;
        float ps = (lane < 8) ? ssp[lane] : 0.0f;
        warp_pair_reduce8(pm, ps);
        if (lane == 0) { g_bm[bid] = pm; g_bs[bid] = ps; }
    }
    grid_barrier();

    // ---------- phase 2: combine 740 e-stat pairs (3KB, fixed order) ; ctx ; a-out ----------
    {
        float pm = -1e30f, ps = 0.0f;
        for (int i = t; i < NBLK; i += TPB) pair_combine(pm, ps, g_bm[i], g_bs[i]);
        warp_pair_reduce32(pm, ps);
        if (lane == 0) { smp[wid] = pm; ssp[wid] = ps; }
        __syncthreads();
        if (wid == 0) {
            float qm = (lane < 8) ? smp[lane] : -1e30f;
            float qs = (lane < 8) ? ssp[lane] : 0.0f;
            warp_pair_reduce8(qm, qs);
            if (lane == 0) { sred[32] = qm; sred[33] = qs; }
        }
        __syncthreads();
    }
    const float M    = sred[32];
    const float invS = 1.0f / sred[33];
    __syncthreads();

    if (bid < 512) {
        // ctx: block = 32 l-rows x 256 cols; h_all re-read is L2-hot
        const int jg = bid & 3, l0 = (bid >> 2) * 32;
        if (t < 32) sbuf[t] = expf(g_e[l0 + t] - M) * invS;
        __syncthreads();
        const int j = jg * 256 + t;
        const float* hp = h_all + (size_t)l0 * H + j;
        float acc = 0.0f;
#pragma unroll 8
        for (int l = 0; l < 32; ++l) acc = fmaf(sbuf[l], hp[(size_t)l * H], acc);
        atomicAdd(&g_cat[H + j], acc);
    } else if (bid < 528) {
        int l = (bid - 512) * 256 + t;
        out[V + H + l] = expf(g_e[l] - M) * invS;   // attention weights output
    }
    grid_barrier();

    // ---------- phase 3: x = new_W @ [emb; c] + new_b ----------
    if (bid < 128) {
        sb4[t]       = reinterpret_cast<const float4*>(g_cat)[t];
        sb4[256 + t] = reinterpret_cast<const float4*>(g_cat)[256 + t];
        __syncthreads();
        float acc = row_dot<512>(reinterpret_cast<const float4*>(new_W) + (size_t)gw * 512, sb4, lane);
        if (lane == 0) g_x[gw] = acc + new_b[gw];
    }
    grid_barrier();

    // ---------- phase 4: gi rows (3 per warp) fused with GRU gates -> h_new ----------
    if (bid < 128) {
        sb4[t] = reinterpret_cast<const float4*>(g_x)[t];
        __syncthreads();
        const float4* Wv = reinterpret_cast<const float4*>(W_ih);
        float d0 = row_dot<256>(Wv + (size_t)gw * 256, sb4, lane);
        float d1 = row_dot<256>(Wv + (size_t)(gw + H) * 256, sb4, lane);
        float d2 = row_dot<256>(Wv + (size_t)(gw + 2 * H) * 256, sb4, lane);
        if (lane == 0) {
            float rr = 1.0f / (1.0f + expf(-(d0 + b_ih[gw] + g_gh[gw])));
            float zz = 1.0f / (1.0f + expf(-(d1 + b_ih[gw + H] + g_gh[gw + H])));
            float nn = tanhf(d2 + b_ih[gw + 2 * H] + rr * g_gh[gw + 2 * H]);
            float hv = (1.0f - zz) * nn + zz * s_bef[gw];
            g_h[gw]    = hv;
            out[V + gw] = hv;
        }
    }
    grid_barrier();

    // ---------- phase 5: logits GEMV, 9 consecutive rows/warp, __ldg stream ----------
    sb4[t] = reinterpret_cast<const float4*>(g_h)[t];
    __syncthreads();

    const int r0 = gw * NROW_LOG;
    float vals[NROW_LOG];
#pragma unroll
    for (int k = 0; k < NROW_LOG; ++k) {
        const int r = r0 + k;
        float s = 0.0f;
        if (r < V) {
            const float4* Wr = reinterpret_cast<const float4*>(out_W) + (size_t)r * 256;
#pragma unroll
            for (int i = 0; i < 8; ++i) {
                float4 w = __ldg(&Wr[lane + i * 32]);
                float4 x = sb4[lane + i * 32];
                s = fmaf(w.x, x.x, s); s = fmaf(w.y, x.y, s);
                s = fmaf(w.z, x.z, s); s = fmaf(w.w, x.w, s);
            }
        }
        vals[k] = s;
    }
#pragma unroll
    for (int k = 0; k < NROW_LOG; ++k) {
        vals[k] = warp_sum(vals[k]);
        if (r0 + k < V) vals[k] += out_b[r0 + k];
    }
    float lm = -1e30f, ls = 0.0f;
#pragma unroll
    for (int k = 0; k < NROW_LOG; ++k)
        if (r0 + k < V) pair_combine(lm, ls, vals[k], 1.0f);

    if (lane == 0) { smp[wid] = lm; ssp[wid] = ls; }
    __syncthreads();
    if (wid == 0) {
        float pm = (lane < 8) ? smp[lane] : -1e30f;
        float ps = (lane < 8) ? ssp[lane] : 0.0f;
        warp_pair_reduce8(pm, ps);
        if (lane == 0) { g_bm[bid] = pm; g_bs[bid] = ps; }
    }
    grid_barrier();

    // ---------- phase 6: combine 740 block pairs redundantly; store final logp ----------
    {
        float pm = -1e30f, ps = 0.0f;
        for (int i = t; i < NBLK; i += TPB) pair_combine(pm, ps, g_bm[i], g_bs[i]);
        warp_pair_reduce32(pm, ps);
        if (lane == 0) { smp[wid] = pm; ssp[wid] = ps; }
        __syncthreads();
        if (wid == 0) {
            float qm = (lane < 8) ? smp[lane] : -1e30f;
            float qs = (lane < 8) ? ssp[lane] : 0.0f;
            warp_pair_reduce8(qm, qs);
            if (lane == 0) sred[34] = qm + logf(qs);
        }
        __syncthreads();
        const float ln = sred[34];
        if (lane == 0) {
#pragma unroll
            for (int k = 0; k < NROW_LOG; ++k)
                if (r0 + k < V) out[r0 + k] = vals[k] - ln;   // only store of logits
        }
    }
}

// ================= launch: single kernel =================
extern "C" void kernel_launch(void* const* d_in, const int* in_sizes, int n_in,
                              void* d_out, int out_size) {
    const int*   y      = (const int*)d_in[0];
    const float* s_bef  = (const float*)d_in[1];
    const float* h_all  = (const float*)d_in[2];
    const float* emb_W  = (const float*)d_in[3];
    const float* alignW = (const float*)d_in[4];
    // d_in[5] align_b: uniform additive shift -> softmax-invariant, dropped
    const float* new_W  = (const float*)d_in[6];
    const float* new_b  = (const float*)d_in[7];
    const float* W_ih   = (const float*)d_in[8];
    const float* b_ih   = (const float*)d_in[9];
    const float* W_hh   = (const float*)d_in[10];
    const float* b_hh   = (const float*)d_in[11];
    const float* out_W  = (const float*)d_in[12];
    const float* out_b  = (const float*)d_in[13];
    float* out = (float*)d_out;  // [logp(V) | h_new(H) | a(L)]

    fused_kernel<<<NBLK, TPB>>>(y, s_bef, h_all, emb_W, alignW, new_W, new_b,
                                W_ih, b_ih, W_hh, b_hh, out_W, out_b, out);
}

// round 12
// speedup vs baseline: 1.3681x; 1.1783x over previous
#include <cuda_runtime.h>

#define H 1024
#define V 50257
#define LCTX 4096

#define NBLK 740            // 148 SMs x 5 co-resident 256-thr blocks -> sw barrier safe
#define TPB  256
#define NWARP (NBLK * 8)    // 5920 warps
#define NROW_LOG 9          // ceil(V / NWARP), consecutive rows per warp

// ---------------- device scratch (allocation-free, 16B aligned) ----------------
__device__ __align__(16) float g_e[LCTX];
__device__ __align__(16) float g_cat[2 * H];
__device__ __align__(16) float g_x[H];
__device__ __align__(16) float g_gh[3 * H];
__device__ __align__(16) float g_h[H];
__device__ float g_bm[NBLK];
__device__ float g_bs[NBLK];
__device__ unsigned g_bar_count = 0;
__device__ unsigned g_bar_gen   = 0;

__device__ __forceinline__ void grid_barrier() {
    __threadfence();
    __syncthreads();
    if (threadIdx.x == 0) {
        unsigned gen = *(volatile unsigned*)&g_bar_gen;
        if (atomicAdd(&g_bar_count, 1u) == NBLK - 1) {
            g_bar_count = 0;
            __threadfence();
            atomicExch(&g_bar_gen, gen + 1);
        } else {
            while (*(volatile unsigned*)&g_bar_gen == gen) { __nanosleep(64); }
        }
        __threadfence();
    }
    __syncthreads();
}

__device__ __forceinline__ float warp_sum(float s) {
#pragma unroll
    for (int o = 16; o; o >>= 1) s += __shfl_xor_sync(0xffffffffu, s, o);
    return s;
}
__device__ __forceinline__ void pair_combine(float& m, float& s, float om, float os) {
    float nm = fmaxf(m, om);
    s = s * expf(m - nm) + os * expf(om - nm);
    m = nm;
}
__device__ __forceinline__ void warp_pair_reduce8(float& m, float& s) {
#pragma unroll
    for (int o = 4; o; o >>= 1) {
        float om = __shfl_xor_sync(0xffffffffu, m, o);
        float os = __shfl_xor_sync(0xffffffffu, s, o);
        pair_combine(m, s, om, os);
    }
}
__device__ __forceinline__ void warp_pair_reduce32(float& m, float& s) {
#pragma unroll
    for (int o = 16; o; o >>= 1) {
        float om = __shfl_xor_sync(0xffffffffu, m, o);
        float os = __shfl_xor_sync(0xffffffffu, s, o);
        pair_combine(m, s, om, os);
    }
}

template <int C4>
__device__ __forceinline__ float row_dot(const float4* __restrict__ row,
                                         const float4* __restrict__ vec, int lane) {
    float s = 0.0f;
#pragma unroll
    for (int i = 0; i < C4 / 32; ++i) {
        float4 w = __ldg(&row[lane + i * 32]);
        float4 x = vec[lane + i * 32];
        s = fmaf(w.x, x.x, s); s = fmaf(w.y, x.y, s);
        s = fmaf(w.z, x.z, s); s = fmaf(w.w, x.w, s);
    }
    return warp_sum(s);
}

// ================= everything in ONE kernel, 5 blocks/SM =================
__global__ void __launch_bounds__(TPB, 5)
fused_kernel(const int* __restrict__ y, const float* __restrict__ s_bef,
             const float* __restrict__ h_all, const float* __restrict__ emb_W,
             const float* __restrict__ alignW, const float* __restrict__ new_W,
             const float* __restrict__ new_b, const float* __restrict__ W_ih,
             const float* __restrict__ b_ih, const float* __restrict__ W_hh,
             const float* __restrict__ b_hh, const float* __restrict__ out_W,
             const float* __restrict__ out_b, float* __restrict__ out) {
    __shared__ float sbuf[2 * H];
    __shared__ float sred[40];
    __shared__ float smp[8], ssp[8];

    const int t    = threadIdx.x;
    const int bid  = blockIdx.x;
    const int wid  = t >> 5;
    const int lane = t & 31;
    const int gw   = bid * 8 + wid;     // 0..5919
    float4* sb4 = reinterpret_cast<float4*>(sbuf);

    // ---------- phase 1: e = h_all@Wh (online stats) ; gh = W_hh@s_prev + b_hh ; setup ----------
    sb4[t]       = reinterpret_cast<const float4*>(alignW)[t];        // Wh
    sb4[256 + t] = reinterpret_cast<const float4*>(s_bef)[t];         // s_prev
    __syncthreads();

    if (bid == 1)
        reinterpret_cast<float4*>(g_cat)[t] =
            reinterpret_cast<const float4*>(emb_W)[(size_t)y[0] * 256 + t];
    if (bid == 2)
        reinterpret_cast<float4*>(g_cat)[256 + t] = make_float4(0.f, 0.f, 0.f, 0.f);

    float em = -1e30f, es = 0.0f;                // this warp's online e-stats (fixed order)
    for (int r = gw; r < LCTX + 3 * H; r += NWARP) {
        float s;
        if (r < LCTX)
            s = row_dot<256>(reinterpret_cast<const float4*>(h_all) + (size_t)r * 256, sb4, lane);
        else
            s = row_dot<256>(reinterpret_cast<const float4*>(W_hh) + (size_t)(r - LCTX) * 256, sb4 + 256, lane);
        if (r < LCTX) {
            if (lane == 0) g_e[r] = s;
            pair_combine(em, es, s, 1.0f);       // s is warp-uniform after warp_sum
        } else if (lane == 0) {
            g_gh[r - LCTX] = s + b_hh[r - LCTX];
        }
    }
    if (lane == 0) { smp[wid] = em; ssp[wid] = es; }
    __syncthreads();
    if (wid == 0) {
        float pm = (lane < 8) ? smp[lane] : -1e30f;
        float ps = (lane < 8) ? ssp[lane] : 0.0f;
        warp_pair_reduce8(pm, ps);
        if (lane == 0) { g_bm[bid] = pm; g_bs[bid] = ps; }
    }
    grid_barrier();

    // ---------- phase 2: combine 740 e-stat pairs (fixed order) ; ctx ; a-out ----------
    {
        float pm = -1e30f, ps = 0.0f;
        for (int i = t; i < NBLK; i += TPB) pair_combine(pm, ps, g_bm[i], g_bs[i]);
        warp_pair_reduce32(pm, ps);
        if (lane == 0) { smp[wid] = pm; ssp[wid] = ps; }
        __syncthreads();
        if (wid == 0) {
            float qm = (lane < 8) ? smp[lane] : -1e30f;
            float qs = (lane < 8) ? ssp[lane] : 0.0f;
            warp_pair_reduce8(qm, qs);
            if (lane == 0) { sred[32] = qm; sred[33] = qs; }
        }
        __syncthreads();
    }
    const float M    = sred[32];
    const float invS = 1.0f / sred[33];
    __syncthreads();

    if (bid < 512) {
        // ctx: block = 32 l-rows x 256 cols; h_all re-read is L2-hot
        const int jg = bid & 3, l0 = (bid >> 2) * 32;
        if (t < 32) sbuf[t] = expf(g_e[l0 + t] - M) * invS;
        __syncthreads();
        const int j = jg * 256 + t;
        const float* hp = h_all + (size_t)l0 * H + j;
        float acc = 0.0f;
#pragma unroll 8
        for (int l = 0; l < 32; ++l) acc = fmaf(sbuf[l], hp[(size_t)l * H], acc);
        atomicAdd(&g_cat[H + j], acc);
    } else if (bid < 528) {
        int l = (bid - 512) * 256 + t;
        out[V + H + l] = expf(g_e[l] - M) * invS;   // attention weights output
    }
    grid_barrier();

    // ---------- phase 3: x = new_W @ [emb; c] + new_b ----------
    if (bid < 128) {
        sb4[t]       = reinterpret_cast<const float4*>(g_cat)[t];
        sb4[256 + t] = reinterpret_cast<const float4*>(g_cat)[256 + t];
        __syncthreads();
        float acc = row_dot<512>(reinterpret_cast<const float4*>(new_W) + (size_t)gw * 512, sb4, lane);
        if (lane == 0) g_x[gw] = acc + new_b[gw];
    }
    grid_barrier();

    // ---------- phase 4: gi rows (3 per warp) fused with GRU gates -> h_new ----------
    if (bid < 128) {
        sb4[t] = reinterpret_cast<const float4*>(g_x)[t];
        __syncthreads();
        const float4* Wv = reinterpret_cast<const float4*>(W_ih);
        float d0 = row_dot<256>(Wv + (size_t)gw * 256, sb4, lane);
        float d1 = row_dot<256>(Wv + (size_t)(gw + H) * 256, sb4, lane);
        float d2 = row_dot<256>(Wv + (size_t)(gw + 2 * H) * 256, sb4, lane);
        if (lane == 0) {
            float rr = 1.0f / (1.0f + expf(-(d0 + b_ih[gw] + g_gh[gw])));
            float zz = 1.0f / (1.0f + expf(-(d1 + b_ih[gw + H] + g_gh[gw + H])));
            float nn = tanhf(d2 + b_ih[gw + 2 * H] + rr * g_gh[gw + 2 * H]);
            float hv = (1.0f - zz) * nn + zz * s_bef[gw];
            g_h[gw]    = hv;
            out[V + gw] = hv;
        }
    }
    grid_barrier();

    // ---------- phase 5: logits GEMV, 9 consecutive rows/warp, __ldcs stream ----------
    sb4[t] = reinterpret_cast<const float4*>(g_h)[t];
    __syncthreads();

    const int r0 = gw * NROW_LOG;
    float vals[NROW_LOG];
#pragma unroll
    for (int k = 0; k < NROW_LOG; ++k) {
        const int r = r0 + k;
        float s = 0.0f;
        if (r < V) {
            const float4* Wr = reinterpret_cast<const float4*>(out_W) + (size_t)r * 256;
#pragma unroll
            for (int i = 0; i < 8; ++i) {
                float4 w = __ldcs(&Wr[lane + i * 32]);
                float4 x = sb4[lane + i * 32];
                s = fmaf(w.x, x.x, s); s = fmaf(w.y, x.y, s);
                s = fmaf(w.z, x.z, s); s = fmaf(w.w, x.w, s);
            }
        }
        vals[k] = s;
    }
#pragma unroll
    for (int k = 0; k < NROW_LOG; ++k) {
        vals[k] = warp_sum(vals[k]);
        if (r0 + k < V) vals[k] += out_b[r0 + k];
    }
    float lm = -1e30f, ls = 0.0f;
#pragma unroll
    for (int k = 0; k < NROW_LOG; ++k)
        if (r0 + k < V) pair_combine(lm, ls, vals[k], 1.0f);

    if (lane == 0) { smp[wid] = lm; ssp[wid] = ls; }
    __syncthreads();
    if (wid == 0) {
        float pm = (lane < 8) ? smp[lane] : -1e30f;
        float ps = (lane < 8) ? ssp[lane] : 0.0f;
        warp_pair_reduce8(pm, ps);
        if (lane == 0) { g_bm[bid] = pm; g_bs[bid] = ps; }
    }
    grid_barrier();

    // ---------- phase 6: combine 740 block pairs redundantly; store final logp ----------
    {
        float pm = -1e30f, ps = 0.0f;
        for (int i = t; i < NBLK; i += TPB) pair_combine(pm, ps, g_bm[i], g_bs[i]);
        warp_pair_reduce32(pm, ps);
        if (lane == 0) { smp[wid] = pm; ssp[wid] = ps; }
        __syncthreads();
        if (wid == 0) {
            float qm = (lane < 8) ? smp[lane] : -1e30f;
            float qs = (lane < 8) ? ssp[lane] : 0.0f;
            warp_pair_reduce8(qm, qs);
            if (lane == 0) sred[34] = qm + logf(qs);
        }
        __syncthreads();
        const float ln = sred[34];
        if (lane == 0) {
#pragma unroll
            for (int k = 0; k < NROW_LOG; ++k)
                if (r0 + k < V) out[r0 + k] = vals[k] - ln;   // only store of logits
        }
    }
}

// ================= launch: single kernel =================
extern "C" void kernel_launch(void* const* d_in, const int* in_sizes, int n_in,
                              void* d_out, int out_size) {
    const int*   y      = (const int*)d_in[0];
    const float* s_bef  = (const float*)d_in[1];
    const float* h_all  = (const float*)d_in[2];
    const float* emb_W  = (const float*)d_in[3];
    const float* alignW = (const float*)d_in[4];
    // d_in[5] align_b: uniform additive shift -> softmax-invariant, dropped
    const float* new_W  = (const float*)d_in[6];
    const float* new_b  = (const float*)d_in[7];
    const float* W_ih   = (const float*)d_in[8];
    const float* b_ih   = (const float*)d_in[9];
    const float* W_hh   = (const float*)d_in[10];
    const float* b_hh   = (const float*)d_in[11];
    const float* out_W  = (const float*)d_in[12];
    const float* out_b  = (const float*)d_in[13];
    float* out = (float*)d_out;  // [logp(V) | h_new(H) | a(L)]

    fused_kernel<<<NBLK, TPB>>>(y, s_bef, h_all, emb_W, alignW, new_W, new_b,
                                W_ih, b_ih, W_hh, b_hh, out_W, out_b, out);
}